// round 1
// baseline (speedup 1.0000x reference)
#include <cuda_runtime.h>
#include <math.h>

// Problem constants
#define S_LEN   1024
#define BATCH   8
#define DMODEL  1024
#define NH      16
#define DHEAD   64
#define NQKV    3072            // 3 * NH * DHEAD
#define MROWS   8192            // S_LEN * BATCH

// ---------------- device scratch (no allocations allowed) ----------------
__device__ float g_Wcat[DMODEL * NQKV];   // (1024, 3072) concat Wq|Wk|Wv, col = which*1024 + h*64 + k
__device__ float g_bcat[NQKV];
__device__ float g_QKV[(size_t)MROWS * NQKV];   // rows = s*B+b
__device__ float g_ctx[(size_t)MROWS * DMODEL]; // attention context, concat heads

// ---------------- weight repack: Wq/Wk/Wv -> one (DM, 3072) matrix ----------------
__global__ void pack_w_kernel(const float* __restrict__ Wq, const float* __restrict__ Wk,
                              const float* __restrict__ Wv, const float* __restrict__ bq,
                              const float* __restrict__ bk, const float* __restrict__ bv) {
    int idx = blockIdx.x * 256 + threadIdx.x;
    const int TOT = NH * DMODEL * DHEAD;  // 1,048,576
    if (idx < TOT) {
        int h = idx >> 16;            // / (1024*64)
        int d = (idx >> 6) & 1023;
        int k = idx & 63;
        int col = h * 64 + k;
        g_Wcat[d * NQKV + col]            = Wq[idx];
        g_Wcat[d * NQKV + 1024 + col]     = Wk[idx];
        g_Wcat[d * NQKV + 2048 + col]     = Wv[idx];
    }
    if (idx < 1024) {
        g_bcat[idx]        = bq[idx];
        g_bcat[1024 + idx] = bk[idx];
        g_bcat[2048 + idx] = bv[idx];
    }
}

// ---------------- fp32 SGEMM: C(M,N) = A(M,K) @ B(K,N) + bias(N) ----------------
// 128x128 block tile, BK=8, 256 threads, 8x8 per-thread micro-tile.
__global__ __launch_bounds__(256) void sgemm_bias(
    const float* __restrict__ A, const float* __restrict__ Bw,
    const float* __restrict__ bias, float* __restrict__ C,
    int M, int N, int K)
{
    __shared__ float As[8][132];   // padded: conflict-free transposed stores
    __shared__ float Bs[8][128];

    int tid  = threadIdx.x;
    int brow = blockIdx.y * 128;
    int bcol = blockIdx.x * 128;

    int a_r = tid >> 1;            // 0..127
    int a_c = (tid & 1) << 2;      // 0 or 4
    int b_r = tid >> 5;            // 0..7
    int b_c = (tid & 31) << 2;     // 0..124

    int trow = (tid >> 4) << 3;    // 0..120
    int tcol = (tid & 15) << 3;    // 0..120

    float acc[8][8];
#pragma unroll
    for (int i = 0; i < 8; i++)
#pragma unroll
        for (int j = 0; j < 8; j++) acc[i][j] = 0.f;

    const float* Aptr = A + (size_t)(brow + a_r) * K + a_c;
    const float* Bptr = Bw + (size_t)b_r * N + bcol + b_c;

    for (int k0 = 0; k0 < K; k0 += 8) {
        float4 av = *(const float4*)(Aptr + k0);
        float4 bv = *(const float4*)(Bptr + (size_t)k0 * N);
        As[a_c + 0][a_r] = av.x;
        As[a_c + 1][a_r] = av.y;
        As[a_c + 2][a_r] = av.z;
        As[a_c + 3][a_r] = av.w;
        *(float4*)&Bs[b_r][b_c] = bv;
        __syncthreads();
#pragma unroll
        for (int kk = 0; kk < 8; kk++) {
            float ar[8], br[8];
            *(float4*)&ar[0] = *(const float4*)&As[kk][trow];
            *(float4*)&ar[4] = *(const float4*)&As[kk][trow + 4];
            *(float4*)&br[0] = *(const float4*)&Bs[kk][tcol];
            *(float4*)&br[4] = *(const float4*)&Bs[kk][tcol + 4];
#pragma unroll
            for (int i = 0; i < 8; i++)
#pragma unroll
                for (int j = 0; j < 8; j++)
                    acc[i][j] += ar[i] * br[j];
        }
        __syncthreads();
    }

#pragma unroll
    for (int i = 0; i < 8; i++) {
        size_t r = (size_t)(brow + trow + i) * N;
#pragma unroll
        for (int j = 0; j < 8; j += 4) {
            int c = bcol + tcol + j;
            float4 o;
            o.x = acc[i][j + 0] + bias[c + 0];
            o.y = acc[i][j + 1] + bias[c + 1];
            o.z = acc[i][j + 2] + bias[c + 2];
            o.w = acc[i][j + 3] + bias[c + 3];
            *(float4*)&C[r + c] = o;
        }
    }
}

// ---------------- causal flash attention ----------------
// Grid (S/64, B, H); 256 threads as 16(tx) x 16(ty); thread owns 4 q-rows x 4 cols.
// smem: qs[64][65], kps[64][65] (K tile, then P tile), vs[64][65]
#define ATT_PAD 65
__global__ __launch_bounds__(256) void attn_kernel() {
    extern __shared__ float sm[];
    float* qs  = sm;
    float* kps = sm + 64 * ATT_PAD;
    float* vs  = sm + 2 * 64 * ATT_PAD;

    int qt = blockIdx.x;
    int b  = blockIdx.y;
    int h  = blockIdx.z;
    int tid = threadIdx.x;
    int tx = tid & 15;
    int ty = tid >> 4;
    int q0 = qt * 64;

    // load q tile, pre-scaled by 1/sqrt(dk)
    for (int i = tid; i < 64 * 64; i += 256) {
        int r = i >> 6, d = i & 63;
        qs[r * ATT_PAD + d] =
            g_QKV[(size_t)((q0 + r) * BATCH + b) * NQKV + h * 64 + d] * 0.125f;
    }

    float o[4][4];
    float m_i[4], l_i[4];
#pragma unroll
    for (int i = 0; i < 4; i++) {
        m_i[i] = -1e30f; l_i[i] = 0.f;
#pragma unroll
        for (int j = 0; j < 4; j++) o[i][j] = 0.f;
    }

    for (int kt = 0; kt <= qt; kt++) {
        __syncthreads();   // previous P tile fully consumed (also covers q load, iter 0)
        for (int i = tid; i < 64 * 64; i += 256) {
            int r = i >> 6, d = i & 63;
            size_t base = (size_t)((kt * 64 + r) * BATCH + b) * NQKV + h * 64 + d;
            kps[r * ATT_PAD + d] = g_QKV[base + 1024];
            vs [r * ATT_PAD + d] = g_QKV[base + 2048];
        }
        __syncthreads();

        // S = q @ k^T  (4x4 per thread)
        float s[4][4];
#pragma unroll
        for (int i = 0; i < 4; i++)
#pragma unroll
            for (int j = 0; j < 4; j++) s[i][j] = 0.f;

#pragma unroll 8
        for (int d = 0; d < 64; d++) {
            float rq[4], rk[4];
#pragma unroll
            for (int i = 0; i < 4; i++) rq[i] = qs[(ty * 4 + i) * ATT_PAD + d];
#pragma unroll
            for (int j = 0; j < 4; j++) rk[j] = kps[(tx * 4 + j) * ATT_PAD + d];
#pragma unroll
            for (int i = 0; i < 4; i++)
#pragma unroll
                for (int j = 0; j < 4; j++)
                    s[i][j] += rq[i] * rk[j];
        }

        if (kt == qt) {
#pragma unroll
            for (int i = 0; i < 4; i++)
#pragma unroll
                for (int j = 0; j < 4; j++)
                    if (tx * 4 + j > ty * 4 + i) s[i][j] = -1e30f;
        }

        // online softmax: row max + row sum (reduce across the 16 tx lanes)
        float mn[4];
#pragma unroll
        for (int i = 0; i < 4; i++) {
            float m = s[i][0];
            m = fmaxf(m, s[i][1]); m = fmaxf(m, s[i][2]); m = fmaxf(m, s[i][3]);
            mn[i] = m;
        }
#pragma unroll
        for (int off = 8; off >= 1; off >>= 1)
#pragma unroll
            for (int i = 0; i < 4; i++)
                mn[i] = fmaxf(mn[i], __shfl_xor_sync(0xffffffffu, mn[i], off, 16));

        float alpha[4], rs[4];
#pragma unroll
        for (int i = 0; i < 4; i++) {
            float mnew = fmaxf(m_i[i], mn[i]);
            alpha[i] = __expf(m_i[i] - mnew);
            m_i[i] = mnew;
            float sum = 0.f;
#pragma unroll
            for (int j = 0; j < 4; j++) {
                s[i][j] = __expf(s[i][j] - mnew);
                sum += s[i][j];
            }
            rs[i] = sum;
        }
#pragma unroll
        for (int off = 8; off >= 1; off >>= 1)
#pragma unroll
            for (int i = 0; i < 4; i++)
                rs[i] += __shfl_xor_sync(0xffffffffu, rs[i], off, 16);
#pragma unroll
        for (int i = 0; i < 4; i++) {
            l_i[i] = l_i[i] * alpha[i] + rs[i];
#pragma unroll
            for (int j = 0; j < 4; j++) o[i][j] *= alpha[i];
        }

        __syncthreads();   // all threads done reading K from kps
#pragma unroll
        for (int i = 0; i < 4; i++)
#pragma unroll
            for (int j = 0; j < 4; j++)
                kps[(ty * 4 + i) * ATT_PAD + tx * 4 + j] = s[i][j];
        __syncthreads();

        // O += P @ V
#pragma unroll 8
        for (int k = 0; k < 64; k++) {
            float rp[4], rv[4];
#pragma unroll
            for (int i = 0; i < 4; i++) rp[i] = kps[(ty * 4 + i) * ATT_PAD + k];
#pragma unroll
            for (int j = 0; j < 4; j++) rv[j] = vs[k * ATT_PAD + tx * 4 + j];
#pragma unroll
            for (int i = 0; i < 4; i++)
#pragma unroll
                for (int j = 0; j < 4; j++)
                    o[i][j] += rp[i] * rv[j];
        }
    }

    // normalize + store context (head-concat layout)
#pragma unroll
    for (int i = 0; i < 4; i++) {
        float inv = 1.f / l_i[i];
#pragma unroll
        for (int j = 0; j < 4; j++) {
            g_ctx[(size_t)((q0 + ty * 4 + i) * BATCH + b) * DMODEL + h * 64 + tx * 4 + j] =
                o[i][j] * inv;
        }
    }
}

// ---------------- launch ----------------
extern "C" void kernel_launch(void* const* d_in, const int* in_sizes, int n_in,
                              void* d_out, int out_size) {
    const float* Q  = (const float*)d_in[0];
    const float* Wq = (const float*)d_in[1];
    const float* bq = (const float*)d_in[2];
    const float* Wk = (const float*)d_in[3];
    const float* bk = (const float*)d_in[4];
    const float* Wv = (const float*)d_in[5];
    const float* bv = (const float*)d_in[6];
    const float* Wo = (const float*)d_in[7];
    const float* bo = (const float*)d_in[8];
    float* out = (float*)d_out;

    float *wcat, *bcat, *qkv, *ctx;
    cudaGetSymbolAddress((void**)&wcat, g_Wcat);
    cudaGetSymbolAddress((void**)&bcat, g_bcat);
    cudaGetSymbolAddress((void**)&qkv,  g_QKV);
    cudaGetSymbolAddress((void**)&ctx,  g_ctx);

    const int attn_smem = 3 * 64 * ATT_PAD * (int)sizeof(float);  // 49,920 B
    cudaFuncSetAttribute(attn_kernel, cudaFuncAttributeMaxDynamicSharedMemorySize, attn_smem);

    // 1) repack weights
    pack_w_kernel<<<4096, 256>>>(Wq, Wk, Wv, bq, bk, bv);

    // 2) fused QKV projection: (8192,1024) @ (1024,3072) + bias
    sgemm_bias<<<dim3(NQKV / 128, MROWS / 128), 256>>>(Q, wcat, bcat, qkv,
                                                       MROWS, NQKV, DMODEL);

    // 3) causal flash attention
    attn_kernel<<<dim3(S_LEN / 64, BATCH, NH), 256, attn_smem>>>();

    // 4) output projection: (8192,1024) @ (1024,1024) + bias -> d_out
    sgemm_bias<<<dim3(DMODEL / 128, MROWS / 128), 256>>>(ctx, Wo, bo, out,
                                                         MROWS, DMODEL, DMODEL);
}

// round 2
// speedup vs baseline: 1.8258x; 1.8258x over previous
#include <cuda_runtime.h>
#include <math.h>
#include <stdint.h>

// Problem constants
#define S_LEN   1024
#define BATCH   8
#define DMODEL  1024
#define NH      16
#define DHEAD   64
#define NQKV    3072
#define MROWS   8192

// ---------------- device scratch ----------------
__device__ float g_Wcat[DMODEL * NQKV];          // tf32-rounded concat Wq|Wk|Wv
__device__ float g_bcat[NQKV];
__device__ float g_Wo[DMODEL * DMODEL];          // tf32-rounded Wo
__device__ float g_Ain[(size_t)MROWS * DMODEL];  // tf32-rounded Q activations
__device__ float g_QKV[(size_t)MROWS * NQKV];
__device__ float g_ctx[(size_t)MROWS * DMODEL];  // tf32-rounded at store

__device__ __forceinline__ float tf32r(float x) {
    uint32_t o;
    asm("cvt.rna.tf32.f32 %0, %1;" : "=r"(o) : "f"(x));
    return __uint_as_float(o);
}

// ---------------- weight repack (+ tf32 round) ----------------
__global__ void pack_w_kernel(const float* __restrict__ Wq, const float* __restrict__ Wk,
                              const float* __restrict__ Wv, const float* __restrict__ bq,
                              const float* __restrict__ bk, const float* __restrict__ bv) {
    int idx = blockIdx.x * 256 + threadIdx.x;
    const int TOT = NH * DMODEL * DHEAD;
    if (idx < TOT) {
        int h = idx >> 16;
        int d = (idx >> 6) & 1023;
        int k = idx & 63;
        int col = h * 64 + k;
        g_Wcat[d * NQKV + col]        = tf32r(Wq[idx]);
        g_Wcat[d * NQKV + 1024 + col] = tf32r(Wk[idx]);
        g_Wcat[d * NQKV + 2048 + col] = tf32r(Wv[idx]);
    }
    if (idx < 1024) {
        g_bcat[idx]        = bq[idx];
        g_bcat[1024 + idx] = bk[idx];
        g_bcat[2048 + idx] = bv[idx];
    }
}

// ---------------- tf32 rounding pass (float4 copy) ----------------
__global__ void round_tf32_kernel(const float* __restrict__ src, float* __restrict__ dst, int n4) {
    int i = blockIdx.x * 256 + threadIdx.x;
    if (i < n4) {
        float4 v = ((const float4*)src)[i];
        v.x = tf32r(v.x); v.y = tf32r(v.y); v.z = tf32r(v.z); v.w = tf32r(v.w);
        ((float4*)dst)[i] = v;
    }
}

// ---------------- TF32 tensor-core GEMM ----------------
// C(M,N) = A(M,K) @ B(K,N) + bias.  Inputs must be pre-rounded to tf32 values.
// 128x128 block tile, BK=32, 256 threads (8 warps as 2x4, warp tile 64x32),
// 2-stage cp.async double buffering.
#define GA_STR 36     // As row stride (floats): bank = lane, conflict-free
#define GB_STR 132    // Bs row stride
#define AS_BUF (128 * GA_STR)
#define BS_BUF (32 * GB_STR)

__global__ __launch_bounds__(256, 2) void gemm_tf32(
    const float* __restrict__ A, const float* __restrict__ Bw,
    const float* __restrict__ bias, float* __restrict__ C,
    int M, int N, int K)
{
    extern __shared__ float sm[];
    float* As = sm;                 // 2 x [128][GA_STR]  (A tile, [m][k])
    float* Bs = sm + 2 * AS_BUF;    // 2 x [32][GB_STR]   (B tile, [k][n])

    int tid  = threadIdx.x;
    int lane = tid & 31;
    int warp = tid >> 5;
    int brow = blockIdx.y * 128;
    int bcol = blockIdx.x * 128;
    int wm   = (warp >> 2) * 64;
    int wn   = (warp & 3) * 32;

    // staging maps
    int ar  = tid >> 1;             // A row 0..127
    int ac4 = (tid & 1) * 4;        // A float4 base idx (0 or 4)
    int bkr = tid >> 3;             // B k-row 0..31
    int bc4 = tid & 7;              // B float4 base idx

    const float* Abase = A + (size_t)(brow + ar) * K;
    const float* Bbase = Bw + bcol;

    float c[4][4][4];
#pragma unroll
    for (int mi = 0; mi < 4; mi++)
#pragma unroll
        for (int ni = 0; ni < 4; ni++)
#pragma unroll
            for (int q = 0; q < 4; q++) c[mi][ni][q] = 0.f;

    uint32_t sAr = (uint32_t)__cvta_generic_to_shared(As) + ar * GA_STR * 4;
    uint32_t sBr = (uint32_t)__cvta_generic_to_shared(Bs) + bkr * GB_STR * 4;

#define STAGE(KT, BUF)                                                                 \
    do {                                                                               \
        int _k0 = (KT) * 32;                                                           \
        uint32_t _sa = sAr + (BUF) * AS_BUF * 4;                                       \
        _Pragma("unroll")                                                              \
        for (int j = 0; j < 4; j++)                                                    \
            asm volatile("cp.async.cg.shared.global [%0], [%1], 16;\n" ::              \
                         "r"(_sa + (ac4 + j) * 16), "l"(Abase + _k0 + (ac4 + j) * 4)); \
        uint32_t _sb = sBr + (BUF) * BS_BUF * 4;                                       \
        const float* _gb = Bbase + (size_t)(_k0 + bkr) * N;                            \
        _Pragma("unroll")                                                              \
        for (int j = 0; j < 4; j++)                                                    \
            asm volatile("cp.async.cg.shared.global [%0], [%1], 16;\n" ::              \
                         "r"(_sb + (bc4 + 8 * j) * 16), "l"(_gb + (bc4 + 8 * j) * 4)); \
        asm volatile("cp.async.commit_group;\n");                                      \
    } while (0)

    int NT = K >> 5;
    STAGE(0, 0);

    for (int kt = 0; kt < NT; kt++) {
        int cur = kt & 1;
        if (kt + 1 < NT) {
            STAGE(kt + 1, cur ^ 1);
            asm volatile("cp.async.wait_group 1;\n");
        } else {
            asm volatile("cp.async.wait_group 0;\n");
        }
        __syncthreads();

        const float* Ab = As + cur * AS_BUF;
        const float* Bb = Bs + cur * BS_BUF;

#pragma unroll
        for (int ks = 0; ks < 32; ks += 8) {
            int kr = ks + (lane & 3);
            uint32_t af[4][4];
#pragma unroll
            for (int mi = 0; mi < 4; mi++) {
                int m = wm + mi * 16 + (lane >> 2);
                af[mi][0] = __float_as_uint(Ab[m * GA_STR + kr]);
                af[mi][1] = __float_as_uint(Ab[(m + 8) * GA_STR + kr]);
                af[mi][2] = __float_as_uint(Ab[m * GA_STR + kr + 4]);
                af[mi][3] = __float_as_uint(Ab[(m + 8) * GA_STR + kr + 4]);
            }
            uint32_t bf[4][2];
#pragma unroll
            for (int ni = 0; ni < 4; ni++) {
                int n = wn + ni * 8 + (lane >> 2);
                bf[ni][0] = __float_as_uint(Bb[kr * GB_STR + n]);
                bf[ni][1] = __float_as_uint(Bb[(kr + 4) * GB_STR + n]);
            }
#pragma unroll
            for (int mi = 0; mi < 4; mi++)
#pragma unroll
                for (int ni = 0; ni < 4; ni++)
                    asm volatile(
                        "mma.sync.aligned.m16n8k8.row.col.f32.tf32.tf32.f32 "
                        "{%0,%1,%2,%3}, {%4,%5,%6,%7}, {%8,%9}, {%0,%1,%2,%3};\n"
                        : "+f"(c[mi][ni][0]), "+f"(c[mi][ni][1]),
                          "+f"(c[mi][ni][2]), "+f"(c[mi][ni][3])
                        : "r"(af[mi][0]), "r"(af[mi][1]), "r"(af[mi][2]), "r"(af[mi][3]),
                          "r"(bf[ni][0]), "r"(bf[ni][1]));
        }
        __syncthreads();
    }

    // epilogue: + bias, float2 stores
#pragma unroll
    for (int mi = 0; mi < 4; mi++) {
        int r0 = brow + wm + mi * 16 + (lane >> 2);
#pragma unroll
        for (int ni = 0; ni < 4; ni++) {
            int col = bcol + wn + ni * 8 + 2 * (lane & 3);
            float bx = bias[col], by = bias[col + 1];
            float2 v0 = make_float2(c[mi][ni][0] + bx, c[mi][ni][1] + by);
            float2 v1 = make_float2(c[mi][ni][2] + bx, c[mi][ni][3] + by);
            *(float2*)&C[(size_t)r0 * N + col] = v0;
            *(float2*)&C[(size_t)(r0 + 8) * N + col] = v1;
        }
    }
}

// ---------------- causal flash attention (SIMT fp32) ----------------
#define ATT_PAD 65
__global__ __launch_bounds__(256) void attn_kernel() {
    extern __shared__ float smatt[];
    float* qs  = smatt;
    float* kps = smatt + 64 * ATT_PAD;
    float* vs  = smatt + 2 * 64 * ATT_PAD;

    int qt = blockIdx.x;
    int b  = blockIdx.y;
    int h  = blockIdx.z;
    int tid = threadIdx.x;
    int tx = tid & 15;
    int ty = tid >> 4;
    int q0 = qt * 64;

    for (int i = tid; i < 64 * 64; i += 256) {
        int r = i >> 6, d = i & 63;
        qs[r * ATT_PAD + d] =
            g_QKV[(size_t)((q0 + r) * BATCH + b) * NQKV + h * 64 + d] * 0.125f;
    }

    float o[4][4];
    float m_i[4], l_i[4];
#pragma unroll
    for (int i = 0; i < 4; i++) {
        m_i[i] = -1e30f; l_i[i] = 0.f;
#pragma unroll
        for (int j = 0; j < 4; j++) o[i][j] = 0.f;
    }

    for (int kt = 0; kt <= qt; kt++) {
        __syncthreads();
        for (int i = tid; i < 64 * 64; i += 256) {
            int r = i >> 6, d = i & 63;
            size_t base = (size_t)((kt * 64 + r) * BATCH + b) * NQKV + h * 64 + d;
            kps[r * ATT_PAD + d] = g_QKV[base + 1024];
            vs [r * ATT_PAD + d] = g_QKV[base + 2048];
        }
        __syncthreads();

        float s[4][4];
#pragma unroll
        for (int i = 0; i < 4; i++)
#pragma unroll
            for (int j = 0; j < 4; j++) s[i][j] = 0.f;

#pragma unroll 8
        for (int d = 0; d < 64; d++) {
            float rq[4], rk[4];
#pragma unroll
            for (int i = 0; i < 4; i++) rq[i] = qs[(ty * 4 + i) * ATT_PAD + d];
#pragma unroll
            for (int j = 0; j < 4; j++) rk[j] = kps[(tx * 4 + j) * ATT_PAD + d];
#pragma unroll
            for (int i = 0; i < 4; i++)
#pragma unroll
                for (int j = 0; j < 4; j++)
                    s[i][j] += rq[i] * rk[j];
        }

        if (kt == qt) {
#pragma unroll
            for (int i = 0; i < 4; i++)
#pragma unroll
                for (int j = 0; j < 4; j++)
                    if (tx * 4 + j > ty * 4 + i) s[i][j] = -1e30f;
        }

        float mn[4];
#pragma unroll
        for (int i = 0; i < 4; i++) {
            float m = s[i][0];
            m = fmaxf(m, s[i][1]); m = fmaxf(m, s[i][2]); m = fmaxf(m, s[i][3]);
            mn[i] = m;
        }
#pragma unroll
        for (int off = 8; off >= 1; off >>= 1)
#pragma unroll
            for (int i = 0; i < 4; i++)
                mn[i] = fmaxf(mn[i], __shfl_xor_sync(0xffffffffu, mn[i], off, 16));

        float alpha[4], rs[4];
#pragma unroll
        for (int i = 0; i < 4; i++) {
            float mnew = fmaxf(m_i[i], mn[i]);
            alpha[i] = __expf(m_i[i] - mnew);
            m_i[i] = mnew;
            float sum = 0.f;
#pragma unroll
            for (int j = 0; j < 4; j++) {
                s[i][j] = __expf(s[i][j] - mnew);
                sum += s[i][j];
            }
            rs[i] = sum;
        }
#pragma unroll
        for (int off = 8; off >= 1; off >>= 1)
#pragma unroll
            for (int i = 0; i < 4; i++)
                rs[i] += __shfl_xor_sync(0xffffffffu, rs[i], off, 16);
#pragma unroll
        for (int i = 0; i < 4; i++) {
            l_i[i] = l_i[i] * alpha[i] + rs[i];
#pragma unroll
            for (int j = 0; j < 4; j++) o[i][j] *= alpha[i];
        }

        __syncthreads();
#pragma unroll
        for (int i = 0; i < 4; i++)
#pragma unroll
            for (int j = 0; j < 4; j++)
                kps[(ty * 4 + i) * ATT_PAD + tx * 4 + j] = s[i][j];
        __syncthreads();

#pragma unroll 8
        for (int k = 0; k < 64; k++) {
            float rp[4], rv[4];
#pragma unroll
            for (int i = 0; i < 4; i++) rp[i] = kps[(ty * 4 + i) * ATT_PAD + k];
#pragma unroll
            for (int j = 0; j < 4; j++) rv[j] = vs[k * ATT_PAD + tx * 4 + j];
#pragma unroll
            for (int i = 0; i < 4; i++)
#pragma unroll
                for (int j = 0; j < 4; j++)
                    o[i][j] += rp[i] * rv[j];
        }
    }

    // normalize + store (tf32-rounded: ctx feeds the tf32 out-proj GEMM)
#pragma unroll
    for (int i = 0; i < 4; i++) {
        float inv = 1.f / l_i[i];
#pragma unroll
        for (int j = 0; j < 4; j++) {
            g_ctx[(size_t)((q0 + ty * 4 + i) * BATCH + b) * DMODEL + h * 64 + tx * 4 + j] =
                tf32r(o[i][j] * inv);
        }
    }
}

// ---------------- launch ----------------
extern "C" void kernel_launch(void* const* d_in, const int* in_sizes, int n_in,
                              void* d_out, int out_size) {
    const float* Q  = (const float*)d_in[0];
    const float* Wq = (const float*)d_in[1];
    const float* bq = (const float*)d_in[2];
    const float* Wk = (const float*)d_in[3];
    const float* bk = (const float*)d_in[4];
    const float* Wv = (const float*)d_in[5];
    const float* bv = (const float*)d_in[6];
    const float* Wo = (const float*)d_in[7];
    const float* bo = (const float*)d_in[8];
    float* out = (float*)d_out;

    float *wcat, *bcat, *wo, *ain, *qkv, *ctx;
    cudaGetSymbolAddress((void**)&wcat, g_Wcat);
    cudaGetSymbolAddress((void**)&bcat, g_bcat);
    cudaGetSymbolAddress((void**)&wo,   g_Wo);
    cudaGetSymbolAddress((void**)&ain,  g_Ain);
    cudaGetSymbolAddress((void**)&qkv,  g_QKV);
    cudaGetSymbolAddress((void**)&ctx,  g_ctx);

    const int gemm_smem = (2 * AS_BUF + 2 * BS_BUF) * (int)sizeof(float); // 70,656 B
    cudaFuncSetAttribute(gemm_tf32, cudaFuncAttributeMaxDynamicSharedMemorySize, gemm_smem);
    const int attn_smem = 3 * 64 * ATT_PAD * (int)sizeof(float);
    cudaFuncSetAttribute(attn_kernel, cudaFuncAttributeMaxDynamicSharedMemorySize, attn_smem);

    // 1) repack + round weights / activations
    pack_w_kernel<<<4096, 256>>>(Wq, Wk, Wv, bq, bk, bv);
    round_tf32_kernel<<<(MROWS * DMODEL / 4 + 255) / 256, 256>>>(Q, ain, MROWS * DMODEL / 4);
    round_tf32_kernel<<<(DMODEL * DMODEL / 4 + 255) / 256, 256>>>(Wo, wo, DMODEL * DMODEL / 4);

    // 2) fused QKV projection (tf32 tensor cores)
    gemm_tf32<<<dim3(NQKV / 128, MROWS / 128), 256, gemm_smem>>>(
        ain, wcat, bcat, qkv, MROWS, NQKV, DMODEL);

    // 3) causal flash attention
    attn_kernel<<<dim3(S_LEN / 64, BATCH, NH), 256, attn_smem>>>();

    // 4) output projection (tf32 tensor cores)
    gemm_tf32<<<dim3(DMODEL / 128, MROWS / 128), 256, gemm_smem>>>(
        ctx, wo, bo, out, MROWS, DMODEL, DMODEL);
}